// round 2
// baseline (speedup 1.0000x reference)
#include <cuda_runtime.h>
#include <cuda_bf16.h>

// Problem constants
#define B_   2
#define N_   2048
#define D_   768
#define H_   12
#define HD_  64
#define M_   (B_*N_)      // 4096 total rows

// Scratch (device globals: no allocation allowed in kernel_launch)
__device__ float g_q[B_*H_*N_*HD_];   // [B,H,N,HD]
__device__ float g_k[B_*H_*N_*HD_];
__device__ float g_v[B_*H_*N_*HD_];
__device__ float g_o[B_*N_*D_];       // attention output, [B,N,D] with D = h*64+hd

// ---------------------------------------------------------------------------
// Tiled SGEMM: C[M x NCOLS] = A[M x 768] @ W[768 x NCOLS] + bias
// MODE 0: epilogue scatters into g_q/g_k/g_v ([B,H,N,HD] layout)
// MODE 1: A is g_o, plain write (with bias) to Cout
// 128x128x16 tiles, 256 threads, 8x8 register micro-tile.
// ---------------------------------------------------------------------------
template<int NCOLS, int MODE>
__global__ __launch_bounds__(256, 2) void gemm_kernel(
    const float* __restrict__ Ain, const float* __restrict__ W,
    const float* __restrict__ bias, float* __restrict__ Cout)
{
    const int BM = 128, BN = 128, BK = 16;
    __shared__ float As[BK][BM + 4];   // [k][m], +4 pad for transposed writes
    __shared__ float Bs[BK][BN];       // [k][n]

    const float* A = (MODE == 1) ? (const float*)g_o : Ain;

    int tid = threadIdx.x;
    int tx = tid & 15, ty = tid >> 4;
    int brow = blockIdx.y * BM;
    int bcol = blockIdx.x * BN;

    float acc[8][8];
    #pragma unroll
    for (int i = 0; i < 8; i++)
        #pragma unroll
        for (int j = 0; j < 8; j++) acc[i][j] = 0.f;

    for (int k0 = 0; k0 < 768; k0 += BK) {
        // Load A tile (BM x BK) as float4, store transposed
        #pragma unroll
        for (int it = 0; it < 2; it++) {
            int idx = tid + it * 256;         // 0..511 float4s
            int r = idx >> 2;                 // 4 float4 per row of 16
            int c = (idx & 3) << 2;
            float4 a = *(const float4*)(A + (size_t)(brow + r) * 768 + k0 + c);
            As[c + 0][r] = a.x; As[c + 1][r] = a.y;
            As[c + 2][r] = a.z; As[c + 3][r] = a.w;
        }
        // Load B tile (BK x BN) as float4, row-major
        #pragma unroll
        for (int it = 0; it < 2; it++) {
            int idx = tid + it * 256;
            int r = idx >> 5;                 // 32 float4 per row of 128
            int c = (idx & 31) << 2;
            *(float4*)(&Bs[r][c]) =
                *(const float4*)(W + (size_t)(k0 + r) * NCOLS + bcol + c);
        }
        __syncthreads();

        #pragma unroll
        for (int kk = 0; kk < BK; kk++) {
            float ar[8], br[8];
            *(float4*)(ar)     = *(float4*)(&As[kk][ty * 4]);
            *(float4*)(ar + 4) = *(float4*)(&As[kk][64 + ty * 4]);
            *(float4*)(br)     = *(float4*)(&Bs[kk][tx * 4]);
            *(float4*)(br + 4) = *(float4*)(&Bs[kk][64 + tx * 4]);
            #pragma unroll
            for (int i = 0; i < 8; i++)
                #pragma unroll
                for (int j = 0; j < 8; j++) acc[i][j] += ar[i] * br[j];
        }
        __syncthreads();
    }

    // Epilogue
    #pragma unroll
    for (int i = 0; i < 8; i++) {
        int row = brow + ((i >> 2) << 6) + ty * 4 + (i & 3);
        #pragma unroll
        for (int j = 0; j < 8; j++) {
            int col = bcol + ((j >> 2) << 6) + tx * 4 + (j & 3);
            float val = acc[i][j] + bias[col];
            if (MODE == 0) {
                int which = col / 768;         // 0=q 1=k 2=v
                int d = col - which * 768;
                int h = d >> 6, hd = d & 63;
                int b = row >> 11, n = row & 2047;
                float* dst = (which == 0) ? g_q : ((which == 1) ? g_k : g_v);
                dst[(((size_t)(b * H_ + h)) * N_ + n) * HD_ + hd] = val;
            } else {
                Cout[(size_t)row * NCOLS + col] = val;
            }
        }
    }
}

// ---------------------------------------------------------------------------
// Fused flash-attention: per block = (64 query rows, one (b,h)).
// Online softmax over 32 key tiles of 64. O accumulators in registers.
// s = (q.k)*scale + bias_table[clip(dist,0,31)][h]; masked keys -> -1e30.
// ---------------------------------------------------------------------------
__global__ __launch_bounds__(256) void attn_kernel(
    const int* __restrict__ dist, const int* __restrict__ mask,
    const float* __restrict__ bias_table)
{
    extern __shared__ float sm[];
    float (*Qs)[65] = (float(*)[65])(sm);          // [d][q]
    float (*Ks)[65] = (float(*)[65])(sm + 4160);   // [d][k]
    float (*Ps)[65] = (float(*)[65])(sm + 8320);   // [q][k]
    float (*Vs)[64] = (float(*)[64])(sm + 12480);  // [k][d]
    float* sm_m = sm + 16576;
    float* sm_l = sm_m + 64;
    float* sm_c = sm_l + 64;
    float* bt   = sm_c + 64;           // 32 bias entries for this head
    int*   msk  = (int*)(bt + 32);     // 64

    int tid = threadIdx.x;
    int tx = tid & 15, ty = tid >> 4;
    int bh = blockIdx.y;
    int b = bh / H_, h = bh - b * H_;
    int q0 = blockIdx.x * 64;
    const float scale = 0.125f;  // 64^-0.5

    size_t base = ((size_t)(b * H_ + h)) * N_ * HD_;

    // Q tile (transposed into smem)
    #pragma unroll
    for (int t = 0; t < 4; t++) {
        int idx4 = tid + t * 256;            // 1024 float4 = 64x64 floats
        int r = idx4 >> 4;
        int d4 = (idx4 & 15) << 2;
        float4 qv = *(const float4*)(g_q + base + (size_t)(q0 + r) * HD_ + d4);
        Qs[d4 + 0][r] = qv.x; Qs[d4 + 1][r] = qv.y;
        Qs[d4 + 2][r] = qv.z; Qs[d4 + 3][r] = qv.w;
    }
    if (tid < 64) { sm_m[tid] = -1e30f; sm_l[tid] = 0.f; }
    if (tid < 32) bt[tid] = bias_table[tid * H_ + h];

    float o[4][4];
    #pragma unroll
    for (int i = 0; i < 4; i++)
        #pragma unroll
        for (int j = 0; j < 4; j++) o[i][j] = 0.f;

    for (int k0 = 0; k0 < N_; k0 += 64) {
        // K (transposed) and V (row-major) tiles
        #pragma unroll
        for (int t = 0; t < 4; t++) {
            int idx4 = tid + t * 256;
            int r = idx4 >> 4;
            int d4 = (idx4 & 15) << 2;
            float4 kv = *(const float4*)(g_k + base + (size_t)(k0 + r) * HD_ + d4);
            Ks[d4 + 0][r] = kv.x; Ks[d4 + 1][r] = kv.y;
            Ks[d4 + 2][r] = kv.z; Ks[d4 + 3][r] = kv.w;
            float4 vv = *(const float4*)(g_v + base + (size_t)(k0 + r) * HD_ + d4);
            *(float4*)(&Vs[r][d4]) = vv;
        }
        if (tid < 64) msk[tid] = mask[b * N_ + k0 + tid];
        __syncthreads();

        // S = Q K^T (4x4 micro-tile; rows q=ty+16i, cols k=tx+16j)
        float s[4][4];
        #pragma unroll
        for (int i = 0; i < 4; i++)
            #pragma unroll
            for (int j = 0; j < 4; j++) s[i][j] = 0.f;
        #pragma unroll 4
        for (int d = 0; d < HD_; d++) {
            float qr[4], kr[4];
            #pragma unroll
            for (int i = 0; i < 4; i++) qr[i] = Qs[d][ty + 16 * i];
            #pragma unroll
            for (int j = 0; j < 4; j++) kr[j] = Ks[d][tx + 16 * j];
            #pragma unroll
            for (int i = 0; i < 4; i++)
                #pragma unroll
                for (int j = 0; j < 4; j++) s[i][j] += qr[i] * kr[j];
        }
        // scale + relative-position bias + key mask -> Ps
        #pragma unroll
        for (int i = 0; i < 4; i++) {
            int q = ty + 16 * i;
            const int* drow = dist + ((size_t)(b * N_) + q0 + q) * N_ + k0;
            #pragma unroll
            for (int j = 0; j < 4; j++) {
                int kk = tx + 16 * j;
                int dd = drow[kk];
                dd = min(max(dd, 0), 31);
                float sv = s[i][j] * scale + bt[dd];
                if (msk[kk]) sv = -1e30f;
                Ps[q][kk] = sv;
            }
        }
        __syncthreads();

        // Online softmax: 8 warps x 8 rows
        {
            int warp = tid >> 5, lane = tid & 31;
            #pragma unroll
            for (int rr = 0; rr < 8; rr++) {
                int q = warp * 8 + rr;
                float v0 = Ps[q][lane], v1 = Ps[q][lane + 32];
                float mx = fmaxf(v0, v1);
                #pragma unroll
                for (int off = 16; off; off >>= 1)
                    mx = fmaxf(mx, __shfl_xor_sync(0xffffffffu, mx, off));
                float mold = sm_m[q];
                float mnew = fmaxf(mold, mx);
                float p0 = __expf(v0 - mnew), p1 = __expf(v1 - mnew);
                Ps[q][lane] = p0; Ps[q][lane + 32] = p1;
                float ssum = p0 + p1;
                #pragma unroll
                for (int off = 16; off; off >>= 1)
                    ssum += __shfl_xor_sync(0xffffffffu, ssum, off);
                if (lane == 0) {
                    float corr = __expf(mold - mnew);
                    sm_c[q] = corr;
                    sm_m[q] = mnew;
                    sm_l[q] = sm_l[q] * corr + ssum;
                }
            }
        }
        __syncthreads();

        // Rescale O, accumulate O += P @ V
        float cr[4];
        #pragma unroll
        for (int i = 0; i < 4; i++) cr[i] = sm_c[ty + 16 * i];
        #pragma unroll
        for (int i = 0; i < 4; i++)
            #pragma unroll
            for (int j = 0; j < 4; j++) o[i][j] *= cr[i];
        #pragma unroll 4
        for (int kk = 0; kk < 64; kk++) {
            float pr[4], vr[4];
            #pragma unroll
            for (int i = 0; i < 4; i++) pr[i] = Ps[ty + 16 * i][kk];
            #pragma unroll
            for (int j = 0; j < 4; j++) vr[j] = Vs[kk][tx + 16 * j];
            #pragma unroll
            for (int i = 0; i < 4; i++)
                #pragma unroll
                for (int j = 0; j < 4; j++) o[i][j] += pr[i] * vr[j];
        }
        __syncthreads();
    }

    // Final normalize, write to g_o in [B,N,D] layout (D index = h*64 + hd)
    float inv[4];
    #pragma unroll
    for (int i = 0; i < 4; i++) inv[i] = 1.f / sm_l[ty + 16 * i];
    #pragma unroll
    for (int i = 0; i < 4; i++) {
        int q = q0 + ty + 16 * i;
        #pragma unroll
        for (int j = 0; j < 4; j++) {
            int c = tx + 16 * j;
            g_o[((size_t)(b * N_) + q) * D_ + h * HD_ + c] = o[i][j] * inv[i];
        }
    }
}

// ---------------------------------------------------------------------------
// Launch
// ---------------------------------------------------------------------------
extern "C" void kernel_launch(void* const* d_in, const int* in_sizes, int n_in,
                              void* d_out, int out_size)
{
    const float* x      = (const float*)d_in[0];   // [B,N,D]
    const int*   dist   = (const int*)  d_in[1];   // [B,N,N] int32
    const int*   mask   = (const int*)  d_in[2];   // [B,N] (bool promoted; nonzero = masked)
    const float* qkv_w  = (const float*)d_in[3];   // [D,3D]
    const float* qkv_b  = (const float*)d_in[4];   // [3D]
    const float* out_w  = (const float*)d_in[5];   // [D,D]
    const float* out_b  = (const float*)d_in[6];   // [D]
    const float* btab   = (const float*)d_in[7];   // [32,H]
    float* out = (float*)d_out;                    // [B,N,D] fp32

    // 1) QKV projection, scattered into [B,H,N,HD] q/k/v
    gemm_kernel<3 * D_, 0><<<dim3((3 * D_) / 128, M_ / 128), 256>>>(
        x, qkv_w, qkv_b, nullptr);

    // 2) Fused attention (flash-style)
    const int ATTN_SMEM = 16864 * 4;  // 67456 B
    cudaFuncSetAttribute(attn_kernel,
                         cudaFuncAttributeMaxDynamicSharedMemorySize, ATTN_SMEM);
    attn_kernel<<<dim3(N_ / 64, B_ * H_), 256, ATTN_SMEM>>>(dist, mask, btab);

    // 3) Output projection
    gemm_kernel<D_, 1><<<dim3(D_ / 128, M_ / 128), 256>>>(
        nullptr, out_w, out_b, out);
}

// round 3
// speedup vs baseline: 2.2521x; 2.2521x over previous
#include <cuda_runtime.h>
#include <cstdint>
#include <cstddef>

// Problem constants
#define B_   2
#define N_   2048
#define D_   768
#define H_   12
#define HD_  64
#define M_   (B_*N_)      // 4096 total rows

// Scratch (device globals: no allocation allowed)
__device__ float g_q[B_*H_*N_*HD_];   // [B,H,N,HD]
__device__ float g_k[B_*H_*N_*HD_];
__device__ float g_v[B_*H_*N_*HD_];
__device__ float g_o[B_*N_*D_];       // attention output, [B,N,D] (D = h*64+hd)

// ---------------------------------------------------------------------------
// tf32 helpers
// ---------------------------------------------------------------------------
__device__ __forceinline__ float tf32r(float x) {
    float r; asm("cvt.rna.tf32.f32 %0, %1;" : "=f"(r) : "f"(x)); return r;
}

// D(16x8,f32) += A(16x8,tf32,row) * B(8x8,tf32,col)
__device__ __forceinline__ void mma8(float c[4], const uint32_t a[4], const uint32_t b[2]) {
    asm volatile(
        "mma.sync.aligned.m16n8k8.row.col.f32.tf32.tf32.f32 "
        "{%0,%1,%2,%3}, {%4,%5,%6,%7}, {%8,%9}, {%0,%1,%2,%3};"
        : "+f"(c[0]), "+f"(c[1]), "+f"(c[2]), "+f"(c[3])
        : "r"(a[0]), "r"(a[1]), "r"(a[2]), "r"(a[3]),
          "r"(b[0]), "r"(b[1]));
}

// ---------------------------------------------------------------------------
// Tensor-core GEMM: C[M x NCOLS] = A[M x 768] @ W[768 x NCOLS] + bias
// Block tile 128x128, BK=32, 8 warps; warp tile 64x32 (4 m16-tiles x 4 n8-tiles)
// MODE 0: scatter epilogue into g_q/g_k/g_v ([B,H,N,HD]); MODE 1: A = g_o, plain store.
// ---------------------------------------------------------------------------
template<int NCOLS, int MODE>
__global__ __launch_bounds__(256, 2) void gemm_tc(
    const float* __restrict__ Ain, const float* __restrict__ W,
    const float* __restrict__ bias, float* __restrict__ Cout)
{
    __shared__ float As[128][36];   // [m][k], pad 4: frag loads conflict-free
    __shared__ float Bs[32][136];   // [k][n], pad 8: frag loads conflict-free

    const float* A = (MODE == 1) ? (const float*)g_o : Ain;

    const int tid  = threadIdx.x;
    const int warp = tid >> 5, lane = tid & 31;
    const int g = lane >> 2, tg = lane & 3;
    const int mw = (warp & 1) << 6;     // 0 / 64
    const int nw = (warp >> 1) << 5;    // 0 / 32 / 64 / 96
    const int brow = blockIdx.y << 7;
    const int bcol = blockIdx.x << 7;

    float acc[4][4][4];
    #pragma unroll
    for (int mt = 0; mt < 4; mt++)
        #pragma unroll
        for (int nt = 0; nt < 4; nt++)
            #pragma unroll
            for (int r = 0; r < 4; r++) acc[mt][nt][r] = 0.f;

    for (int k0 = 0; k0 < 768; k0 += 32) {
        // A tile 128x32 (1024 float4, 4 per thread)
        #pragma unroll
        for (int it = 0; it < 4; it++) {
            int idx = tid + (it << 8);
            int r = idx >> 3, c = (idx & 7) << 2;
            float4 v = *(const float4*)(A + (size_t)(brow + r) * 768 + k0 + c);
            As[r][c + 0] = tf32r(v.x); As[r][c + 1] = tf32r(v.y);
            As[r][c + 2] = tf32r(v.z); As[r][c + 3] = tf32r(v.w);
        }
        // B tile 32x128
        #pragma unroll
        for (int it = 0; it < 4; it++) {
            int idx = tid + (it << 8);
            int r = idx >> 5, c = (idx & 31) << 2;
            float4 v = *(const float4*)(W + (size_t)(k0 + r) * NCOLS + bcol + c);
            Bs[r][c + 0] = tf32r(v.x); Bs[r][c + 1] = tf32r(v.y);
            Bs[r][c + 2] = tf32r(v.z); Bs[r][c + 3] = tf32r(v.w);
        }
        __syncthreads();

        #pragma unroll
        for (int kk = 0; kk < 32; kk += 8) {
            uint32_t bf[4][2];
            #pragma unroll
            for (int nt = 0; nt < 4; nt++) {
                int col = nw + (nt << 3) + g;
                bf[nt][0] = __float_as_uint(Bs[kk + tg][col]);
                bf[nt][1] = __float_as_uint(Bs[kk + tg + 4][col]);
            }
            #pragma unroll
            for (int mt = 0; mt < 4; mt++) {
                uint32_t af[4];
                int r0 = mw + (mt << 4) + g;
                af[0] = __float_as_uint(As[r0][kk + tg]);
                af[1] = __float_as_uint(As[r0 + 8][kk + tg]);
                af[2] = __float_as_uint(As[r0][kk + tg + 4]);
                af[3] = __float_as_uint(As[r0 + 8][kk + tg + 4]);
                #pragma unroll
                for (int nt = 0; nt < 4; nt++) mma8(acc[mt][nt], af, bf[nt]);
            }
        }
        __syncthreads();
    }

    // Epilogue: acc reg r -> (row + (r>=2?8:0), col + (r&1))
    #pragma unroll
    for (int mt = 0; mt < 4; mt++) {
        #pragma unroll
        for (int nt = 0; nt < 4; nt++) {
            #pragma unroll
            for (int r = 0; r < 4; r++) {
                int row = brow + mw + (mt << 4) + g + ((r >> 1) << 3);
                int col = bcol + nw + (nt << 3) + (tg << 1) + (r & 1);
                float val = acc[mt][nt][r] + bias[col];
                if (MODE == 0) {
                    int which = col / 768;            // 0=q 1=k 2=v
                    int d = col - which * 768;
                    int h = d >> 6, hd = d & 63;
                    int b = row >> 11, n = row & 2047;
                    float* dst = (which == 0) ? g_q : ((which == 1) ? g_k : g_v);
                    dst[(((size_t)(b * H_ + h)) * N_ + n) * HD_ + hd] = val;
                } else {
                    Cout[(size_t)row * NCOLS + col] = val;
                }
            }
        }
    }
}

// ---------------------------------------------------------------------------
// Fused flash-attention with tf32 tensor cores.
// Block = 64 q-rows x one (b,h); 8 warps (4 q-groups x 2 col-halves).
// Per key-tile: S = QK^T (mma) -> smem; softmax pass (bias/mask/online max);
// P (tf32) -> smem; O += P@V (mma), O frags in registers.
// ---------------------------------------------------------------------------
__global__ __launch_bounds__(256) void attn_tc(
    const int* __restrict__ dist, const int* __restrict__ mask,
    const float* __restrict__ bias_table)
{
    extern __shared__ float sm[];
    float* Qs   = sm;            // [64][68]  (q, d) tf32
    float* Ks   = sm + 4352;     // [64][68]  (k, d) tf32
    float* Ps   = sm + 8704;     // [64][68]  (q, k) scores / probs
    float* Vs   = sm + 13056;    // [64][72]  (k, d) tf32 (pad 8 for B-frag)
    float* sm_m = sm + 17664;    // [64]
    float* sm_l = sm + 17728;    // [64]
    float* sm_c = sm + 17792;    // [64]
    float* bt   = sm + 17856;    // [32]
    int*   msk  = (int*)(sm + 17888);  // [64]
    int*   Ds   = (int*)(sm + 17952);  // [64][68]
    // total floats: 17952 + 4352 = 22304  -> 89216 B

    const int tid  = threadIdx.x;
    const int warp = tid >> 5, lane = tid & 31;
    const int g = lane >> 2, tg = lane & 3;
    const int bh = blockIdx.y;
    const int b = bh / H_, h = bh - b * H_;
    const int q0 = blockIdx.x << 6;
    const float scale = 0.125f;  // 64^-0.5
    const size_t base = ((size_t)(b * H_ + h)) * N_ * HD_;

    const int qo = (warp & 3) << 4;   // 0/16/32/48
    const int no = (warp >> 2) << 5;  // 0/32 (key cols for S, d cols for PV)

    // Q tile (tf32-rounded) once
    #pragma unroll
    for (int it = 0; it < 4; it++) {
        int idx = tid + (it << 8);
        int r = idx >> 4, c = (idx & 15) << 2;
        float4 v = *(const float4*)(g_q + base + (size_t)(q0 + r) * HD_ + c);
        float* q = Qs + r * 68 + c;
        q[0] = tf32r(v.x); q[1] = tf32r(v.y); q[2] = tf32r(v.z); q[3] = tf32r(v.w);
    }
    if (tid < 64) { sm_m[tid] = -1e30f; sm_l[tid] = 0.f; }
    if (tid < 32) bt[tid] = bias_table[tid * H_ + h];

    float o[4][4];
    #pragma unroll
    for (int nt = 0; nt < 4; nt++)
        #pragma unroll
        for (int r = 0; r < 4; r++) o[nt][r] = 0.f;

    for (int k0 = 0; k0 < N_; k0 += 64) {
        __syncthreads();  // previous PV done before K/V/Ps/Ds overwritten

        // K, V, dist tiles
        #pragma unroll
        for (int it = 0; it < 4; it++) {
            int idx = tid + (it << 8);
            int r = idx >> 4, c = (idx & 15) << 2;
            float4 kv = *(const float4*)(g_k + base + (size_t)(k0 + r) * HD_ + c);
            float* kd = Ks + r * 68 + c;
            kd[0] = tf32r(kv.x); kd[1] = tf32r(kv.y); kd[2] = tf32r(kv.z); kd[3] = tf32r(kv.w);
            float4 vv = *(const float4*)(g_v + base + (size_t)(k0 + r) * HD_ + c);
            float* vd = Vs + r * 72 + c;
            vd[0] = tf32r(vv.x); vd[1] = tf32r(vv.y); vd[2] = tf32r(vv.z); vd[3] = tf32r(vv.w);
            int4 dv = *(const int4*)(dist + ((size_t)(b * N_) + q0 + r) * N_ + k0 + c);
            int* dd = Ds + r * 68 + c;
            dd[0] = dv.x; dd[1] = dv.y; dd[2] = dv.z; dd[3] = dv.w;
        }
        if (tid < 64) msk[tid] = mask[b * N_ + k0 + tid];
        __syncthreads();

        // ---- S = Q K^T (raw, unscaled) ----
        float s[4][4];
        #pragma unroll
        for (int nt = 0; nt < 4; nt++)
            #pragma unroll
            for (int r = 0; r < 4; r++) s[nt][r] = 0.f;

        #pragma unroll
        for (int d = 0; d < 64; d += 8) {
            uint32_t af[4];
            const float* qa = Qs + (qo + g) * 68 + d + tg;
            af[0] = __float_as_uint(qa[0]);
            af[1] = __float_as_uint(qa[8 * 68]);
            af[2] = __float_as_uint(qa[4]);
            af[3] = __float_as_uint(qa[8 * 68 + 4]);
            #pragma unroll
            for (int nt = 0; nt < 4; nt++) {
                uint32_t bf[2];
                const float* kb = Ks + (no + (nt << 3) + g) * 68 + d + tg;
                bf[0] = __float_as_uint(kb[0]);
                bf[1] = __float_as_uint(kb[4]);
                mma8(s[nt], af, bf);
            }
        }
        // store raw scores
        #pragma unroll
        for (int nt = 0; nt < 4; nt++) {
            float* p = Ps + (qo + g) * 68 + no + (nt << 3) + (tg << 1);
            p[0] = s[nt][0];          p[1] = s[nt][1];
            p[8 * 68] = s[nt][2];     p[8 * 68 + 1] = s[nt][3];
        }
        __syncthreads();

        // ---- online softmax: scale + rel-pos bias + mask (8 warps x 8 rows) ----
        #pragma unroll
        for (int rr = 0; rr < 8; rr++) {
            int q = (warp << 3) + rr;
            float* pr = Ps + q * 68;
            const int* dr = Ds + q * 68;
            int d0 = dr[lane];      d0 = min(max(d0, 0), 31);
            int d1 = dr[lane + 32]; d1 = min(max(d1, 0), 31);
            float v0 = pr[lane] * scale + bt[d0];
            float v1 = pr[lane + 32] * scale + bt[d1];
            if (msk[lane])      v0 = -1e30f;
            if (msk[lane + 32]) v1 = -1e30f;
            float mx = fmaxf(v0, v1);
            #pragma unroll
            for (int off = 16; off; off >>= 1)
                mx = fmaxf(mx, __shfl_xor_sync(0xffffffffu, mx, off));
            float mold = sm_m[q];
            float mnew = fmaxf(mold, mx);
            float p0 = __expf(v0 - mnew), p1 = __expf(v1 - mnew);
            pr[lane] = tf32r(p0);
            pr[lane + 32] = tf32r(p1);
            float ssum = p0 + p1;
            #pragma unroll
            for (int off = 16; off; off >>= 1)
                ssum += __shfl_xor_sync(0xffffffffu, ssum, off);
            if (lane == 0) {
                float corr = __expf(mold - mnew);
                sm_c[q] = corr; sm_m[q] = mnew;
                sm_l[q] = sm_l[q] * corr + ssum;
            }
        }
        __syncthreads();

        // ---- rescale O, O += P @ V ----
        float clo = sm_c[qo + g], chi = sm_c[qo + g + 8];
        #pragma unroll
        for (int nt = 0; nt < 4; nt++) {
            o[nt][0] *= clo; o[nt][1] *= clo;
            o[nt][2] *= chi; o[nt][3] *= chi;
        }
        #pragma unroll
        for (int k = 0; k < 64; k += 8) {
            uint32_t af[4];
            const float* pa = Ps + (qo + g) * 68 + k + tg;
            af[0] = __float_as_uint(pa[0]);
            af[1] = __float_as_uint(pa[8 * 68]);
            af[2] = __float_as_uint(pa[4]);
            af[3] = __float_as_uint(pa[8 * 68 + 4]);
            #pragma unroll
            for (int nt = 0; nt < 4; nt++) {
                uint32_t bf[2];
                const float* vb = Vs + (k + tg) * 72 + no + (nt << 3) + g;
                bf[0] = __float_as_uint(vb[0]);
                bf[1] = __float_as_uint(vb[4 * 72]);
                mma8(o[nt], af, bf);
            }
        }
    }

    // Final normalize + write to g_o ([B,N,D], D index = h*64 + d)
    float ilo = 1.f / sm_l[qo + g], ihi = 1.f / sm_l[qo + g + 8];
    #pragma unroll
    for (int nt = 0; nt < 4; nt++) {
        int d = h * HD_ + no + (nt << 3) + (tg << 1);
        float* dst = g_o + ((size_t)(b * N_) + q0 + qo + g) * D_ + d;
        dst[0] = o[nt][0] * ilo;
        dst[1] = o[nt][1] * ilo;
        dst[8 * D_] = o[nt][2] * ihi;
        dst[8 * D_ + 1] = o[nt][3] * ihi;
    }
}

// ---------------------------------------------------------------------------
// Launch
// ---------------------------------------------------------------------------
extern "C" void kernel_launch(void* const* d_in, const int* in_sizes, int n_in,
                              void* d_out, int out_size)
{
    const float* x      = (const float*)d_in[0];   // [B,N,D]
    const int*   dist   = (const int*)  d_in[1];   // [B,N,N]
    const int*   mask   = (const int*)  d_in[2];   // [B,N] nonzero = masked
    const float* qkv_w  = (const float*)d_in[3];   // [D,3D]
    const float* qkv_b  = (const float*)d_in[4];   // [3D]
    const float* out_w  = (const float*)d_in[5];   // [D,D]
    const float* out_b  = (const float*)d_in[6];   // [D]
    const float* btab   = (const float*)d_in[7];   // [32,H]
    float* out = (float*)d_out;                    // [B,N,D] fp32

    // 1) QKV projection (tensor cores), scatter into [B,H,N,HD]
    gemm_tc<3 * D_, 0><<<dim3((3 * D_) / 128, M_ / 128), 256>>>(
        x, qkv_w, qkv_b, nullptr);

    // 2) Fused flash attention (tensor cores)
    const int ATTN_SMEM = 22304 * 4;  // 89216 B
    cudaFuncSetAttribute(attn_tc,
                         cudaFuncAttributeMaxDynamicSharedMemorySize, ATTN_SMEM);
    attn_tc<<<dim3(N_ / 64, B_ * H_), 256, ATTN_SMEM>>>(dist, mask, btab);

    // 3) Output projection (tensor cores)
    gemm_tc<D_, 1><<<dim3(D_ / 128, M_ / 128), 256>>>(
        nullptr, out_w, out_b, out);
}

// round 6
// speedup vs baseline: 2.4907x; 1.1059x over previous
#include <cuda_runtime.h>
#include <cstdint>
#include <cstddef>

// Problem constants
#define B_   2
#define N_   2048
#define D_   768
#define H_   12
#define HD_  64
#define M_   (B_*N_)      // 4096 rows

// Scratch (device globals)
__device__ float   g_q[B_*H_*N_*HD_];   // [B,H,N,HD] (tf32-valued)
__device__ float   g_k[B_*H_*N_*HD_];
__device__ float   g_v[B_*H_*N_*HD_];
__device__ float   g_o[B_*N_*D_];       // attention out (tf32-valued)
__device__ uint8_t g_d8[(size_t)B_*N_*N_];  // clipped dist, 8.4MB (L2-resident)
__device__ float   g_xr[M_*D_];         // rna-rounded x
__device__ float   g_wqkv[D_*3*D_];     // rna-rounded qkv_w
__device__ float   g_wout[D_*D_];       // rna-rounded out_w

// ---------------------------------------------------------------------------
// helpers
// ---------------------------------------------------------------------------
__device__ __forceinline__ float tf32r(float x) {
    float r; asm("cvt.rna.tf32.f32 %0, %1;" : "=f"(r) : "f"(x)); return r;
}
__device__ __forceinline__ void mma8(float c[4], const uint32_t a[4], const uint32_t b[2]) {
    asm volatile(
        "mma.sync.aligned.m16n8k8.row.col.f32.tf32.tf32.f32 "
        "{%0,%1,%2,%3}, {%4,%5,%6,%7}, {%8,%9}, {%0,%1,%2,%3};"
        : "+f"(c[0]), "+f"(c[1]), "+f"(c[2]), "+f"(c[3])
        : "r"(a[0]), "r"(a[1]), "r"(a[2]), "r"(a[3]), "r"(b[0]), "r"(b[1]));
}
__device__ __forceinline__ void cpa16(void* dst, const void* src) {
    uint32_t a = (uint32_t)__cvta_generic_to_shared(dst);
    asm volatile("cp.async.cg.shared.global [%0], [%1], 16;" :: "r"(a), "l"(src));
}
__device__ __forceinline__ void cpa_commit() { asm volatile("cp.async.commit_group;"); }
__device__ __forceinline__ void cpa_wait0()  { asm volatile("cp.async.wait_group 0;"); }

// ---------------------------------------------------------------------------
// pre-passes
// ---------------------------------------------------------------------------
__global__ __launch_bounds__(256) void pack_dist(const int* __restrict__ dist) {
    size_t i = ((size_t)blockIdx.x * 256 + threadIdx.x) * 4;
    int4 v = *(const int4*)(dist + i);
    uchar4 o;
    o.x = (uint8_t)min(max(v.x, 0), 31);
    o.y = (uint8_t)min(max(v.y, 0), 31);
    o.z = (uint8_t)min(max(v.z, 0), 31);
    o.w = (uint8_t)min(max(v.w, 0), 31);
    *(uchar4*)(g_d8 + i) = o;
}

__global__ __launch_bounds__(256) void round_tf32(const float* __restrict__ src,
                                                  float* __restrict__ dst) {
    size_t i = ((size_t)blockIdx.x * 256 + threadIdx.x) * 4;
    float4 v = *(const float4*)(src + i);
    v.x = tf32r(v.x); v.y = tf32r(v.y); v.z = tf32r(v.z); v.w = tf32r(v.w);
    *(float4*)(dst + i) = v;
}

// ---------------------------------------------------------------------------
// TC GEMM, cp.async double-buffered. C[M x NCOLS] = A[M x 768] @ W + bias.
// Operands must be pre-rounded to tf32 values.
// MODE 0: scatter tf32r(C) to g_q/g_k/g_v; MODE 1: A = g_o, plain fp32 store.
// ---------------------------------------------------------------------------
template<int NCOLS, int MODE>
__global__ __launch_bounds__(256, 2) void gemm_tc(
    const float* __restrict__ Ain, const float* __restrict__ W,
    const float* __restrict__ bias, float* __restrict__ Cout)
{
    __shared__ float As[2][128][36];
    __shared__ float Bs[2][32][136];

    const float* A = (MODE == 1) ? (const float*)g_o : Ain;

    const int tid  = threadIdx.x;
    const int warp = tid >> 5, lane = tid & 31;
    const int g = lane >> 2, tg = lane & 3;
    const int mw = (warp & 1) << 6;
    const int nw = (warp >> 1) << 5;
    const int brow = blockIdx.y << 7;
    const int bcol = blockIdx.x << 7;

    float acc[4][4][4];
    #pragma unroll
    for (int mt = 0; mt < 4; mt++)
        #pragma unroll
        for (int nt = 0; nt < 4; nt++)
            #pragma unroll
            for (int r = 0; r < 4; r++) acc[mt][nt][r] = 0.f;

    auto load_tiles = [&](int buf, int k0) {
        #pragma unroll
        for (int it = 0; it < 4; it++) {
            int idx = tid + (it << 8);
            int r = idx >> 3, c = (idx & 7) << 2;
            cpa16(&As[buf][r][c], A + (size_t)(brow + r) * 768 + k0 + c);
        }
        #pragma unroll
        for (int it = 0; it < 4; it++) {
            int idx = tid + (it << 8);
            int r = idx >> 5, c = (idx & 31) << 2;
            cpa16(&Bs[buf][r][c], W + (size_t)(k0 + r) * NCOLS + bcol + c);
        }
        cpa_commit();
    };

    load_tiles(0, 0);

    for (int kt = 0; kt < 24; kt++) {
        int buf = kt & 1;
        cpa_wait0();
        __syncthreads();
        if (kt + 1 < 24) load_tiles(buf ^ 1, (kt + 1) << 5);

        #pragma unroll
        for (int kk = 0; kk < 32; kk += 8) {
            uint32_t bf[4][2];
            #pragma unroll
            for (int nt = 0; nt < 4; nt++) {
                int col = nw + (nt << 3) + g;
                bf[nt][0] = __float_as_uint(Bs[buf][kk + tg][col]);
                bf[nt][1] = __float_as_uint(Bs[buf][kk + tg + 4][col]);
            }
            #pragma unroll
            for (int mt = 0; mt < 4; mt++) {
                uint32_t af[4];
                int r0 = mw + (mt << 4) + g;
                af[0] = __float_as_uint(As[buf][r0][kk + tg]);
                af[1] = __float_as_uint(As[buf][r0 + 8][kk + tg]);
                af[2] = __float_as_uint(As[buf][r0][kk + tg + 4]);
                af[3] = __float_as_uint(As[buf][r0 + 8][kk + tg + 4]);
                #pragma unroll
                for (int nt = 0; nt < 4; nt++) mma8(acc[mt][nt], af, bf[nt]);
            }
        }
        __syncthreads();
    }

    #pragma unroll
    for (int mt = 0; mt < 4; mt++) {
        #pragma unroll
        for (int nt = 0; nt < 4; nt++) {
            #pragma unroll
            for (int r = 0; r < 4; r++) {
                int row = brow + mw + (mt << 4) + g + ((r >> 1) << 3);
                int col = bcol + nw + (nt << 3) + (tg << 1) + (r & 1);
                float val = acc[mt][nt][r] + bias[col];
                if (MODE == 0) {
                    int which = col / 768;
                    int d = col - which * 768;
                    int h = d >> 6, hd = d & 63;
                    int b = row >> 11, n = row & 2047;
                    float* dst = (which == 0) ? g_q : ((which == 1) ? g_k : g_v);
                    dst[(((size_t)(b * H_ + h)) * N_ + n) * HD_ + hd] = tf32r(val);
                } else {
                    Cout[(size_t)row * NCOLS + col] = val;
                }
            }
        }
    }
}

// ---------------------------------------------------------------------------
// Fused flash attention, tf32 MMA, cp.async double-buffered K/V,
// dist read as uint8 straight from L2 in the softmax pass.
// Block = 64 q-rows x one (b,h); 8 warps (4 q-groups x 2 halves).
// Q/K/V arrive tf32-valued (rounded at QKV-GEMM epilogue).
// ---------------------------------------------------------------------------
__global__ __launch_bounds__(256, 2) void attn_tc(
    const int* __restrict__ mask, const float* __restrict__ bias_table)
{
    extern __shared__ float sm[];
    float* Qs   = sm;                          // [64][68]
    float* Ksb  = sm + 4352;                   // 2 x [64][68]
    float* Vsb  = sm + 13056;                  // 2 x [64][72]
    float* Ps   = sm + 22272;                  // [64][68]
    float* sm_m = sm + 26624;                  // [64]
    float* sm_l = sm + 26688;                  // [64]
    float* sm_c = sm + 26752;                  // [64]
    float* bt   = sm + 26816;                  // [32]
    // total 26848 floats = 107392 B

    const int tid  = threadIdx.x;
    const int warp = tid >> 5, lane = tid & 31;
    const int g = lane >> 2, tg = lane & 3;
    const int bh = blockIdx.y;
    const int b = bh / H_, h = bh - b * H_;
    const int q0 = blockIdx.x << 6;
    const float scale = 0.125f;
    const size_t base = ((size_t)(b * H_ + h)) * N_ * HD_;
    const uint8_t* d8q = g_d8 + ((size_t)(b * N_) + q0) * N_;

    const int qo = (warp & 3) << 4;
    const int no = (warp >> 2) << 5;

    if (tid < 64) { sm_m[tid] = -1e30f; sm_l[tid] = 0.f; }
    if (tid < 32) bt[tid] = bias_table[tid * H_ + h];

    // Q tile + first K/V tile (one cp.async group)
    #pragma unroll
    for (int it = 0; it < 4; it++) {
        int idx = tid + (it << 8);
        int r = idx >> 4, c = (idx & 15) << 2;
        cpa16(Qs + r * 68 + c, g_q + base + (size_t)(q0 + r) * HD_ + c);
        cpa16(Ksb + r * 68 + c, g_k + base + (size_t)r * HD_ + c);
        cpa16(Vsb + r * 72 + c, g_v + base + (size_t)r * HD_ + c);
    }
    cpa_commit();

    float o[4][4];
    #pragma unroll
    for (int nt = 0; nt < 4; nt++)
        #pragma unroll
        for (int r = 0; r < 4; r++) o[nt][r] = 0.f;

    for (int t = 0; t < 32; t++) {
        const int buf = t & 1;
        const int k0 = t << 6;
        float* Ks = Ksb + buf * 4352;
        float* Vs = Vsb + buf * 4608;

        cpa_wait0();
        __syncthreads();

        // ---- S = Q K^T ----
        float s[4][4];
        #pragma unroll
        for (int nt = 0; nt < 4; nt++)
            #pragma unroll
            for (int r = 0; r < 4; r++) s[nt][r] = 0.f;
        #pragma unroll
        for (int d = 0; d < 64; d += 8) {
            uint32_t af[4];
            const float* qa = Qs + (qo + g) * 68 + d + tg;
            af[0] = __float_as_uint(qa[0]);
            af[1] = __float_as_uint(qa[8 * 68]);
            af[2] = __float_as_uint(qa[4]);
            af[3] = __float_as_uint(qa[8 * 68 + 4]);
            #pragma unroll
            for (int nt = 0; nt < 4; nt++) {
                uint32_t bfr[2];
                const float* kb = Ks + (no + (nt << 3) + g) * 68 + d + tg;
                bfr[0] = __float_as_uint(kb[0]);
                bfr[1] = __float_as_uint(kb[4]);
                mma8(s[nt], af, bfr);
            }
        }
        #pragma unroll
        for (int nt = 0; nt < 4; nt++) {
            float* p = Ps + (qo + g) * 68 + no + (nt << 3) + (tg << 1);
            p[0] = s[nt][0];          p[1] = s[nt][1];
            p[8 * 68] = s[nt][2];     p[8 * 68 + 1] = s[nt][3];
        }
        __syncthreads();

        // prefetch next K/V during softmax
        if (t + 1 < 32) {
            float* Kn = Ksb + (buf ^ 1) * 4352;
            float* Vn = Vsb + (buf ^ 1) * 4608;
            const size_t koff = base + (size_t)(k0 + 64) * HD_;
            #pragma unroll
            for (int it = 0; it < 4; it++) {
                int idx = tid + (it << 8);
                int r = idx >> 4, c = (idx & 15) << 2;
                cpa16(Kn + r * 68 + c, g_k + koff + (size_t)r * HD_ + c);
                cpa16(Vn + r * 72 + c, g_v + koff + (size_t)r * HD_ + c);
            }
            cpa_commit();
        }

        // ---- online softmax (dist bytes + mask from L2) ----
        {
            const int mbase = b * N_ + k0;
            const int m0 = __ldg(mask + mbase + lane);
            const int m1 = __ldg(mask + mbase + lane + 32);
            const uint8_t* d8t = d8q + k0;
            #pragma unroll
            for (int rr = 0; rr < 8; rr++) {
                int q = (warp << 3) + rr;
                float* pr = Ps + q * 68;
                const uint8_t* dr = d8t + (size_t)q * N_;
                int d0 = __ldg(dr + lane);
                int d1 = __ldg(dr + lane + 32);
                float v0 = pr[lane] * scale + bt[d0];
                float v1 = pr[lane + 32] * scale + bt[d1];
                if (m0) v0 = -1e30f;
                if (m1) v1 = -1e30f;
                float mx = fmaxf(v0, v1);
                #pragma unroll
                for (int off = 16; off; off >>= 1)
                    mx = fmaxf(mx, __shfl_xor_sync(0xffffffffu, mx, off));
                float mold = sm_m[q];
                float mnew = fmaxf(mold, mx);
                float p0 = __expf(v0 - mnew), p1 = __expf(v1 - mnew);
                pr[lane] = tf32r(p0);
                pr[lane + 32] = tf32r(p1);
                float ssum = p0 + p1;
                #pragma unroll
                for (int off = 16; off; off >>= 1)
                    ssum += __shfl_xor_sync(0xffffffffu, ssum, off);
                if (lane == 0) {
                    float corr = __expf(mold - mnew);
                    sm_c[q] = corr; sm_m[q] = mnew;
                    sm_l[q] = sm_l[q] * corr + ssum;
                }
            }
        }
        __syncthreads();

        // ---- rescale O, O += P @ V ----
        float clo = sm_c[qo + g], chi = sm_c[qo + g + 8];
        #pragma unroll
        for (int nt = 0; nt < 4; nt++) {
            o[nt][0] *= clo; o[nt][1] *= clo;
            o[nt][2] *= chi; o[nt][3] *= chi;
        }
        #pragma unroll
        for (int k = 0; k < 64; k += 8) {
            uint32_t af[4];
            const float* pa = Ps + (qo + g) * 68 + k + tg;
            af[0] = __float_as_uint(pa[0]);
            af[1] = __float_as_uint(pa[8 * 68]);
            af[2] = __float_as_uint(pa[4]);
            af[3] = __float_as_uint(pa[8 * 68 + 4]);
            #pragma unroll
            for (int nt = 0; nt < 4; nt++) {
                uint32_t bfr[2];
                const float* vb = Vs + (k + tg) * 72 + no + (nt << 3) + g;
                bfr[0] = __float_as_uint(vb[0]);
                bfr[1] = __float_as_uint(vb[4 * 72]);
                mma8(o[nt], af, bfr);
            }
        }
    }

    // Final normalize + write (tf32-rounded: feeds out-proj MMA as A operand)
    float ilo = 1.f / sm_l[qo + g], ihi = 1.f / sm_l[qo + g + 8];
    #pragma unroll
    for (int nt = 0; nt < 4; nt++) {
        int d = h * HD_ + no + (nt << 3) + (tg << 1);
        float* dst = g_o + ((size_t)(b * N_) + q0 + qo + g) * D_ + d;
        dst[0] = tf32r(o[nt][0] * ilo);
        dst[1] = tf32r(o[nt][1] * ilo);
        dst[8 * D_] = tf32r(o[nt][2] * ihi);
        dst[8 * D_ + 1] = tf32r(o[nt][3] * ihi);
    }
}

// ---------------------------------------------------------------------------
// Launch
// ---------------------------------------------------------------------------
extern "C" void kernel_launch(void* const* d_in, const int* in_sizes, int n_in,
                              void* d_out, int out_size)
{
    const float* x      = (const float*)d_in[0];
    const int*   dist   = (const int*)  d_in[1];
    const int*   mask   = (const int*)  d_in[2];
    const float* qkv_w  = (const float*)d_in[3];
    const float* qkv_b  = (const float*)d_in[4];
    const float* out_w  = (const float*)d_in[5];
    const float* out_b  = (const float*)d_in[6];
    const float* btab   = (const float*)d_in[7];
    float* out = (float*)d_out;

    // pre-passes: pack dist to u8; rna-round GEMM operands
    pack_dist<<<(B_ * N_ * N_) / (4 * 256), 256>>>(dist);
    {
        float* xr, *wq, *wo;
        cudaGetSymbolAddress((void**)&xr, g_xr);
        cudaGetSymbolAddress((void**)&wq, g_wqkv);
        cudaGetSymbolAddress((void**)&wo, g_wout);
        round_tf32<<<(M_ * D_) / 1024, 256>>>(x, xr);
        round_tf32<<<(D_ * 3 * D_) / 1024, 256>>>(qkv_w, wq);
        round_tf32<<<(D_ * D_) / 1024, 256>>>(out_w, wo);

        // QKV projection (pre-rounded operands)
        gemm_tc<3 * D_, 0><<<dim3((3 * D_) / 128, M_ / 128), 256>>>(
            xr, wq, qkv_b, nullptr);

        // fused attention
        const int ATTN_SMEM = 26848 * 4;  // 107392 B
        cudaFuncSetAttribute(attn_tc,
                             cudaFuncAttributeMaxDynamicSharedMemorySize, ATTN_SMEM);
        attn_tc<<<dim3(N_ / 64, B_ * H_), 256, ATTN_SMEM>>>(mask, btab);

        // output projection (A = g_o already tf32-valued)
        gemm_tc<D_, 1><<<dim3(D_ / 128, M_ / 128), 256>>>(
            nullptr, wo, out_b, out);
    }
}